// round 4
// baseline (speedup 1.0000x reference)
#include <cuda_runtime.h>
#include <math.h>

// FullPairwise neighbor list: M=8 molecules, N=1024 atoms, cutoff 5.2.
// Output (float32 buffer): [2, P] flat atom indices written as floats
// (row 0: i's, row 1: j's), pairs ordered lexicographically by
// (molecule, i, j); trailing elements (incl. the zeros(3) output) zeroed.
//
// Single O(N^2) enumeration pass -> per-(row, col-tile) compact lists in
// static scratch -> flat scan over (m,i,tile) counts (== (m,i,j) order) ->
// tiny gather into d_out.

#define NMOL 8
#define NATM 1024
#define TS 128                 // column tile size
#define NTILE (NATM / TS)      // 8
#define NROWS (NMOL * NATM)    // 8192
#define NRT (NROWS * NTILE)    // 65536 (row, tile) cells
#define SLOTS 32               // max pairs per (row, tile); Poisson(~2.8) mean
#define CUTOFF_F 5.2f
#define C2_LO 27.0399f         // sqrtf(C2_LO) <= 5.2f guaranteed
#define C2_HI 27.0401f         // sqrtf(x) > 5.2f for all x > C2_HI guaranteed

__device__ int g_cnt[NRT];
__device__ int g_off[NRT];
__device__ int g_list[(size_t)NRT * SLOTS];   // 8 MB scratch
__device__ int g_total;

__device__ __forceinline__ bool in_cutoff(float d2) {
    // Branch-free fast path; correctly-rounded sqrtf only in the tiny
    // ambiguous band (preserves exact reference semantics incl. NaN-exclusion).
    bool in = d2 <= C2_LO;
    if (!in && d2 <= C2_HI) in = (sqrtf(d2) <= CUTOFF_F);
    return in;
}

__global__ void enum_kernel(const int* __restrict__ species,
                            const float* __restrict__ coords) {
    __shared__ float4 s[TS];
    const int m = blockIdx.x, rs = blockIdx.y, ct = blockIdx.z;
    const int i = rs * TS + threadIdx.x;
    const int grow = m * NATM + i;           // flat row id == output i-value
    const int rt = grow * NTILE + ct;

    if (ct < rs) {                           // strictly below diagonal: empty
        g_cnt[rt] = 0;
        return;
    }

    const int jbase = ct * TS;
    const float nanv = __int_as_float(0x7fc00000);

    // Stage column tile
    {
        const int ga = m * NATM + jbase + threadIdx.x;
        const float* c = coords + (size_t)ga * 3;
        float x = c[0], y = c[1], z = c[2];
        if (species[ga] == -1) { x = nanv; y = nanv; z = nanv; }
        s[threadIdx.x] = make_float4(x, y, z, 0.0f);
    }
    __syncthreads();

    // My row coordinate
    float cx, cy, cz;
    {
        const float* c = coords + (size_t)grow * 3;
        cx = c[0]; cy = c[1]; cz = c[2];
        if (species[grow] == -1) { cx = nanv; cy = nanv; cz = nanv; }
    }

    const int lstart = (ct == rs) ? (threadIdx.x + 1) : 0;
    int cnt = 0;
    int* __restrict__ lst = &g_list[(size_t)rt * SLOTS];
    const int jflat_base = m * NATM + jbase;

#pragma unroll 4
    for (int l = lstart; l < TS; l++) {
        float4 cj = s[l];
        float dx = cx - cj.x;
        float dy = cy - cj.y;
        float dz = cz - cj.z;
        float d2 = fmaf(dx, dx, fmaf(dy, dy, dz * dz));
        if (in_cutoff(d2)) {
            if (cnt < SLOTS) lst[cnt] = jflat_base + l;
            cnt++;
        }
    }
    g_cnt[rt] = (cnt < SLOTS) ? cnt : SLOTS;
}

// One block, 1024 threads, 64 cells/thread: flat exclusive scan of 65536.
__global__ void scan_kernel() {
    __shared__ int sh[1024];
    const int t = threadIdx.x;
    const int base = t * 64;
    int sum = 0;
#pragma unroll
    for (int k = 0; k < 64; k++) sum += g_cnt[base + k];
    sh[t] = sum;
    __syncthreads();
    for (int off = 1; off < 1024; off <<= 1) {
        int v = (t >= off) ? sh[t - off] : 0;
        __syncthreads();
        sh[t] += v;
        __syncthreads();
    }
    int excl = sh[t] - sum;
#pragma unroll
    for (int k = 0; k < 64; k++) {
        int c = g_cnt[base + k];
        g_off[base + k] = excl;
        excl += c;
    }
    if (t == 1023) g_total = sh[t];
}

// One thread per (row, tile) cell: copy its list into the output (as floats).
__global__ void emit_kernel(float* __restrict__ out) {
    const int rt = blockIdx.x * blockDim.x + threadIdx.x;
    if (rt >= NRT) return;
    const int cnt = g_cnt[rt];
    if (cnt == 0) return;
    const int off = g_off[rt];
    const int total = g_total;
    const float rowf = (float)(rt >> 3);      // flat i value
    const int* __restrict__ lst = &g_list[(size_t)rt * SLOTS];
    for (int k = 0; k < cnt; k++) {
        out[off + k] = rowf;
        out[total + off + k] = (float)lst[k];
    }
}

// Zero everything past the 2*P index payload (covers the zeros(3) tail).
__global__ void tail_kernel(float* __restrict__ out, int out_size) {
    const int idx = blockIdx.x * blockDim.x + threadIdx.x;
    if (idx < out_size && idx >= 2 * g_total) out[idx] = 0.0f;
}

extern "C" void kernel_launch(void* const* d_in, const int* in_sizes, int n_in,
                              void* d_out, int out_size) {
    const int* species = (const int*)d_in[0];
    const float* coords = (const float*)d_in[1];
    float* out = (float*)d_out;

    enum_kernel<<<dim3(NMOL, NATM / TS, NTILE), TS>>>(species, coords);
    scan_kernel<<<1, 1024>>>();
    emit_kernel<<<NRT / 256, 256>>>(out);
    int nb = (out_size + 255) / 256;
    if (nb > 0) tail_kernel<<<nb, 256>>>(out, out_size);
}

// round 6
// speedup vs baseline: 3.1845x; 3.1845x over previous
#include <cuda_runtime.h>
#include <math.h>

// FullPairwise neighbor list: M=8 molecules, N=1024 atoms, cutoff 5.2.
// Output (float32 buffer): [2, P] flat atom indices written as floats
// (row 0: i's, row 1: j's), pairs ordered lexicographically by
// (molecule, i, j); trailing elements (incl. the zeros(3) output) zeroed.
//
// enum (single O(N^2) pass -> per-(row,col-tile) lists + counts)
//  -> coalesced warp-scan over 65536 cells (== (m,i,j) order)
//  -> emit gather + tail zero (fused).

#define NMOL 8
#define NATM 1024
#define TS 128                 // column tile size
#define NTILE (NATM / TS)      // 8
#define NROWS (NMOL * NATM)    // 8192
#define NRT (NROWS * NTILE)    // 65536 (row, tile) cells
#define SLOTS 32               // max pairs per (row, tile)
#define CUTOFF_F 5.2f
#define C2_LO 27.0399f         // sqrtf(C2_LO) <= 5.2f guaranteed
#define C2_HI 27.0401f         // sqrtf(x) > 5.2f for all x > C2_HI guaranteed

__device__ int g_cnt[NRT];
__device__ int g_off[NRT];          // warp-local exclusive offsets
__device__ int g_warpBase[32];      // per-scan-warp global base (2048 cells each)
__device__ int g_list[(size_t)NRT * SLOTS];   // 8 MB scratch
__device__ int g_total;

__device__ __forceinline__ bool in_cutoff(float d2) {
    // Fast squared-distance test; correctly-rounded sqrtf only in the tiny
    // ambiguous band (preserves exact reference semantics incl. NaN-exclusion).
    bool in = d2 <= C2_LO;
    if (!in && d2 <= C2_HI) in = (sqrtf(d2) <= CUTOFF_F);
    return in;
}

__global__ void enum_kernel(const int* __restrict__ species,
                            const float* __restrict__ coords) {
    __shared__ float4 s[TS];
    const int m = blockIdx.x, rs = blockIdx.y, ct = blockIdx.z;
    const int i = rs * TS + threadIdx.x;
    const int grow = m * NATM + i;           // flat row id == output i-value
    const int rt = grow * NTILE + ct;

    if (ct < rs) {                           // strictly below diagonal: empty
        g_cnt[rt] = 0;
        return;
    }

    const int jbase = ct * TS;
    const float nanv = __int_as_float(0x7fc00000);

    // Stage column tile
    {
        const int ga = m * NATM + jbase + threadIdx.x;
        const float* c = coords + (size_t)ga * 3;
        float x = c[0], y = c[1], z = c[2];
        if (species[ga] == -1) { x = nanv; y = nanv; z = nanv; }
        s[threadIdx.x] = make_float4(x, y, z, 0.0f);
    }
    __syncthreads();

    // My row coordinate
    float cx, cy, cz;
    {
        const float* c = coords + (size_t)grow * 3;
        cx = c[0]; cy = c[1]; cz = c[2];
        if (species[grow] == -1) { cx = nanv; cy = nanv; cz = nanv; }
    }

    const int lstart = (ct == rs) ? (threadIdx.x + 1) : 0;
    int cnt = 0;
    int* __restrict__ lst = &g_list[(size_t)rt * SLOTS];
    const int jflat_base = m * NATM + jbase;

#pragma unroll 8
    for (int l = lstart; l < TS; l++) {
        float4 cj = s[l];
        float dx = cx - cj.x;
        float dy = cy - cj.y;
        float dz = cz - cj.z;
        float d2 = fmaf(dz, dz, fmaf(dy, dy, dx * dx));
        if (in_cutoff(d2)) {
            if (cnt < SLOTS) lst[cnt] = jflat_base + l;
            cnt++;
        }
    }
    g_cnt[rt] = (cnt < SLOTS) ? cnt : SLOTS;
}

// One block, 1024 threads = 32 warps. Warp w scans its 2048 contiguous cells
// with coalesced loads + shfl scans; global warp bases resolved separately
// and applied lazily in emit (single pass over g_cnt/g_off).
__global__ void scan_kernel() {
    const unsigned FULL = 0xFFFFFFFFu;
    const int w = threadIdx.x >> 5;
    const int lane = threadIdx.x & 31;
    const int base = w * 2048;

    int running = 0;
    for (int it = 0; it < 64; it++) {
        const int idx = base + it * 32 + lane;
        int v = g_cnt[idx];
        int s = v;
#pragma unroll
        for (int off = 1; off < 32; off <<= 1) {
            int t = __shfl_up_sync(FULL, s, off);
            if (lane >= off) s += t;
        }
        g_off[idx] = running + s - v;            // warp-local exclusive
        running += __shfl_sync(FULL, s, 31);     // warp chunk total so far
    }

    __shared__ int wt[32];
    if (lane == 0) wt[w] = running;
    __syncthreads();

    if (w == 0) {
        int v = wt[lane];
        int s = v;
#pragma unroll
        for (int off = 1; off < 32; off <<= 1) {
            int t = __shfl_up_sync(FULL, s, off);
            if (lane >= off) s += t;
        }
        g_warpBase[lane] = s - v;                // exclusive base per scan-warp
        if (lane == 31) g_total = s;
    }
}

// One thread per (row, tile) cell copies its list; grid-stride loop zeroes
// everything past the 2*P index payload (covers the zeros(3) tail).
__global__ void emit_kernel(float* __restrict__ out, int out_size) {
    const int tid = blockIdx.x * blockDim.x + threadIdx.x;
    const int total = g_total;

    if (tid < NRT) {
        const int cnt = g_cnt[tid];
        if (cnt) {
            const int off = g_off[tid] + g_warpBase[tid >> 11];
            const float rowf = (float)(tid >> 3);     // flat i value
            const int* __restrict__ lst = &g_list[(size_t)tid * SLOTS];
            for (int k = 0; k < cnt; k++) {
                out[off + k] = rowf;
                out[total + off + k] = (float)lst[k];
            }
        }
    }

    const int stride = gridDim.x * blockDim.x;
    for (int idx = tid; idx < out_size; idx += stride)
        if (idx >= 2 * total) out[idx] = 0.0f;
}

extern "C" void kernel_launch(void* const* d_in, const int* in_sizes, int n_in,
                              void* d_out, int out_size) {
    const int* species = (const int*)d_in[0];
    const float* coords = (const float*)d_in[1];
    float* out = (float*)d_out;

    enum_kernel<<<dim3(NMOL, NATM / TS, NTILE), TS>>>(species, coords);
    scan_kernel<<<1, 1024>>>();
    emit_kernel<<<NRT / 256, 256>>>(out, out_size);
}